// round 15
// baseline (speedup 1.0000x reference)
#include <cuda_runtime.h>

#define FEATURES   2048
#define F4         (FEATURES / 4)     // 512 float4 per row
#define SCALE      4.0f
#define TPB        512
#define UNROLL     8
#define PER_BLOCK  (TPB * UNROLL)     // 4096 float4 per chunk
#define NUM_SMS    152                // GB300
#define CTAS_PER_SM 2                 // 512 thr, ~58 regs -> 2 CTAs/SM
#define GRID       (NUM_SMS * CTAS_PER_SM)   // 304 persistent CTAs, one wave

// out = sigmoid(SCALE * (x * w[f] + b[f])) over [32768, 2048] fp32. HBM-bound.
//
// Persistent one-wave grid: 304 CTAs grid-stride over 4096 chunks, so the
// per-SM LDG queue never drains at wave boundaries (stores are fire-and-
// forget; next chunk's 8 front-batched LDG.128 issue immediately).
// Chunk stride is a multiple of F4 -> feature index == tid forever:
// one register-resident (w,b) pair per thread for the whole kernel.
// Sigmoid via MUFU.TANH: sigmoid(4t) = 0.5 + 0.5*tanh(2t), 2 folded into w/b.

__device__ __forceinline__ float tanh_approx(float z) {
    float t;
    asm("tanh.approx.f32 %0, %1;" : "=f"(t) : "f"(z));
    return t;
}

__global__ void __launch_bounds__(TPB) onetoone_sigmoid_persist(
    const float4* __restrict__ x,
    const float4* __restrict__ w,
    const float4* __restrict__ b,
    float4* __restrict__ out,
    int nchunks)
{
    const int tid = threadIdx.x;                  // 0..511 == feature vec4 idx

    // One (w,b) pair per thread for the whole run; fold SCALE/2 = 2.0 once.
    float4 wv = __ldg(&w[tid]);
    float4 bv = __ldg(&b[tid]);
    wv.x *= 2.0f; wv.y *= 2.0f; wv.z *= 2.0f; wv.w *= 2.0f;
    bv.x *= 2.0f; bv.y *= 2.0f; bv.z *= 2.0f; bv.w *= 2.0f;

    for (int c = blockIdx.x; c < nchunks; c += gridDim.x) {
        const int base = c * PER_BLOCK + tid;     // total4 < 2^31, int is fine

        // Front-batched independent loads (MLP_p1 = 8).
        float4 xv[UNROLL];
        #pragma unroll
        for (int u = 0; u < UNROLL; u++)
            xv[u] = __ldcs(&x[base + u * F4]);

        #pragma unroll
        for (int u = 0; u < UNROLL; u++) {
            float4 r;
            r.x = fmaf(tanh_approx(fmaf(xv[u].x, wv.x, bv.x)), 0.5f, 0.5f);
            r.y = fmaf(tanh_approx(fmaf(xv[u].y, wv.y, bv.y)), 0.5f, 0.5f);
            r.z = fmaf(tanh_approx(fmaf(xv[u].z, wv.z, bv.z)), 0.5f, 0.5f);
            r.w = fmaf(tanh_approx(fmaf(xv[u].w, wv.w, bv.w)), 0.5f, 0.5f);
            __stcs(&out[base + u * F4], r);
        }
    }
}

// Generic guarded fallback (only used if sizes ever change).
__global__ void __launch_bounds__(256) onetoone_sigmoid_generic(
    const float4* __restrict__ x,
    const float4* __restrict__ w,
    const float4* __restrict__ b,
    float4* __restrict__ out,
    int total4)
{
    int i = blockIdx.x * blockDim.x + threadIdx.x;
    if (i >= total4) return;
    int fi = i & (F4 - 1);
    float4 xv = __ldcs(&x[i]);
    float4 wv = __ldg(&w[fi]);
    float4 bv = __ldg(&b[fi]);
    float4 r;
    r.x = fmaf(tanh_approx(2.0f * fmaf(xv.x, wv.x, bv.x)), 0.5f, 0.5f);
    r.y = fmaf(tanh_approx(2.0f * fmaf(xv.y, wv.y, bv.y)), 0.5f, 0.5f);
    r.z = fmaf(tanh_approx(2.0f * fmaf(xv.z, wv.z, bv.z)), 0.5f, 0.5f);
    r.w = fmaf(tanh_approx(2.0f * fmaf(xv.w, wv.w, bv.w)), 0.5f, 0.5f);
    __stcs(&out[i], r);
}

extern "C" void kernel_launch(void* const* d_in, const int* in_sizes, int n_in,
                              void* d_out, int out_size)
{
    const float4* x = (const float4*)d_in[0];   // input  [N, FEATURES] fp32
    const float4* w = (const float4*)d_in[1];   // weight [FEATURES]    fp32
    const float4* b = (const float4*)d_in[2];   // bias   [FEATURES]    fp32
    float4* out = (float4*)d_out;

    int total4 = out_size / 4;                  // 16,777,216
    if ((total4 % PER_BLOCK) == 0) {
        int nchunks = total4 / PER_BLOCK;       // 4096
        int grid = GRID < nchunks ? GRID : nchunks;
        onetoone_sigmoid_persist<<<grid, TPB>>>(x, w, b, out, nchunks);
    } else {
        int blocks = (total4 + 255) / 256;
        onetoone_sigmoid_generic<<<blocks, 256>>>(x, w, b, out, total4);
    }
}

// round 16
// speedup vs baseline: 1.1108x; 1.1108x over previous
#include <cuda_runtime.h>

#define FEATURES   2048
#define F4         (FEATURES / 4)     // 512 float4 per row
#define F8         (FEATURES / 8)     // 256 vec8  per row
#define SCALE      4.0f
#define TPB        512
#define UNROLL     4                  // 4 x vec8 = 128 B per thread
#define CHUNK8     (TPB * UNROLL)     // 2048 vec8 per block = 8 rows

// out = sigmoid(SCALE * (x * w[f] + b[f])) over [32768, 2048] fp32. HBM-bound.
//
// 256-bit global accesses (sm_100+): 4 x LDG.256 / 4 x STG.256 per thread —
// same bytes as 8 x 128-bit, but half the LSU issues and half the L1tex
// queue entries. Flat grid (persistent variant regressed in R14).
// u-stride = TPB = 2 rows -> vec8 feature index f8 = tid & 255 is
// loop-invariant: one register-resident vec8 (w,b) pair, SCALE/2 pre-folded.
// Sigmoid via MUFU.TANH: sigmoid(4t) = 0.5 + 0.5*tanh(2t).

__device__ __forceinline__ float tanh_approx(float z) {
    float t;
    asm("tanh.approx.f32 %0, %1;" : "=f"(t) : "f"(z));
    return t;
}

__device__ __forceinline__ void ldg256_cs(const float4* p, float4& a, float4& c) {
    asm volatile("ld.global.cs.v8.f32 {%0,%1,%2,%3,%4,%5,%6,%7}, [%8];"
        : "=f"(a.x), "=f"(a.y), "=f"(a.z), "=f"(a.w),
          "=f"(c.x), "=f"(c.y), "=f"(c.z), "=f"(c.w)
        : "l"(p));
}

__device__ __forceinline__ void stg256_cs(float4* p, const float4& a, const float4& c) {
    asm volatile("st.global.cs.v8.f32 [%0], {%1,%2,%3,%4,%5,%6,%7,%8};"
        :: "l"(p),
           "f"(a.x), "f"(a.y), "f"(a.z), "f"(a.w),
           "f"(c.x), "f"(c.y), "f"(c.z), "f"(c.w)
        : "memory");
}

__global__ void __launch_bounds__(TPB) onetoone_sigmoid_v8(
    const float4* __restrict__ x,
    const float4* __restrict__ w,
    const float4* __restrict__ b,
    float4* __restrict__ out)
{
    const int tid = threadIdx.x;            // 0..511
    const int f8  = tid & (F8 - 1);         // vec8 feature index, loop-invariant

    // One vec8 (w,b) pair per thread; fold SCALE/2 = 2.0 once.
    float4 w0 = __ldg(&w[2 * f8]);
    float4 w1 = __ldg(&w[2 * f8 + 1]);
    float4 b0 = __ldg(&b[2 * f8]);
    float4 b1 = __ldg(&b[2 * f8 + 1]);
    w0.x *= 2.0f; w0.y *= 2.0f; w0.z *= 2.0f; w0.w *= 2.0f;
    w1.x *= 2.0f; w1.y *= 2.0f; w1.z *= 2.0f; w1.w *= 2.0f;
    b0.x *= 2.0f; b0.y *= 2.0f; b0.z *= 2.0f; b0.w *= 2.0f;
    b1.x *= 2.0f; b1.y *= 2.0f; b1.z *= 2.0f; b1.w *= 2.0f;

    const int base8 = blockIdx.x * CHUNK8 + tid;   // vec8 units

    // Front-batched independent 256-bit loads (4 x LDG.256).
    float4 xa[UNROLL], xc[UNROLL];
    #pragma unroll
    for (int u = 0; u < UNROLL; u++)
        ldg256_cs(x + 2 * (base8 + u * TPB), xa[u], xc[u]);

    #pragma unroll
    for (int u = 0; u < UNROLL; u++) {
        float4 ra, rc;
        ra.x = fmaf(tanh_approx(fmaf(xa[u].x, w0.x, b0.x)), 0.5f, 0.5f);
        ra.y = fmaf(tanh_approx(fmaf(xa[u].y, w0.y, b0.y)), 0.5f, 0.5f);
        ra.z = fmaf(tanh_approx(fmaf(xa[u].z, w0.z, b0.z)), 0.5f, 0.5f);
        ra.w = fmaf(tanh_approx(fmaf(xa[u].w, w0.w, b0.w)), 0.5f, 0.5f);
        rc.x = fmaf(tanh_approx(fmaf(xc[u].x, w1.x, b1.x)), 0.5f, 0.5f);
        rc.y = fmaf(tanh_approx(fmaf(xc[u].y, w1.y, b1.y)), 0.5f, 0.5f);
        rc.z = fmaf(tanh_approx(fmaf(xc[u].z, w1.z, b1.z)), 0.5f, 0.5f);
        rc.w = fmaf(tanh_approx(fmaf(xc[u].w, w1.w, b1.w)), 0.5f, 0.5f);
        stg256_cs(out + 2 * (base8 + u * TPB), ra, rc);
    }
}

// Generic guarded fallback (only used if sizes ever change).
__global__ void __launch_bounds__(256) onetoone_sigmoid_generic(
    const float4* __restrict__ x,
    const float4* __restrict__ w,
    const float4* __restrict__ b,
    float4* __restrict__ out,
    int total4)
{
    int i = blockIdx.x * blockDim.x + threadIdx.x;
    if (i >= total4) return;
    int fi = i & (F4 - 1);
    float4 xv = __ldcs(&x[i]);
    float4 wv = __ldg(&w[fi]);
    float4 bv = __ldg(&b[fi]);
    float4 r;
    r.x = fmaf(tanh_approx(2.0f * fmaf(xv.x, wv.x, bv.x)), 0.5f, 0.5f);
    r.y = fmaf(tanh_approx(2.0f * fmaf(xv.y, wv.y, bv.y)), 0.5f, 0.5f);
    r.z = fmaf(tanh_approx(2.0f * fmaf(xv.z, wv.z, bv.z)), 0.5f, 0.5f);
    r.w = fmaf(tanh_approx(2.0f * fmaf(xv.w, wv.w, bv.w)), 0.5f, 0.5f);
    __stcs(&out[i], r);
}

extern "C" void kernel_launch(void* const* d_in, const int* in_sizes, int n_in,
                              void* d_out, int out_size)
{
    const float4* x = (const float4*)d_in[0];   // input  [N, FEATURES] fp32
    const float4* w = (const float4*)d_in[1];   // weight [FEATURES]    fp32
    const float4* b = (const float4*)d_in[2];   // bias   [FEATURES]    fp32
    float4* out = (float4*)d_out;

    int total8 = out_size / 8;                  // 8,388,608 vec8
    if ((total8 % CHUNK8) == 0 && (out_size % FEATURES) == 0) {
        int blocks = total8 / CHUNK8;           // 4096
        onetoone_sigmoid_v8<<<blocks, TPB>>>(x, w, b, out);
    } else {
        int total4 = out_size / 4;
        int blocks = (total4 + 255) / 256;
        onetoone_sigmoid_generic<<<blocks, 256>>>(x, w, b, out, total4);
    }
}